// round 11
// baseline (speedup 1.0000x reference)
#include <cuda_runtime.h>
#include <cuda_bf16.h>
#include <math.h>
#include <stdint.h>

// Problem dims
#define BB   128
#define TT   512
#define FF   784
#define HH   256
#define NG   1024   // 4*H
#define CC   10
#define BN_EPS 1e-3f

// K1 GEMM tiling
#define BKC  16
#define NCHK (FF / BKC)   // 49

// Scratch (device globals; no runtime allocation allowed)
__device__ float  g_xw[(size_t)BB * TT * NG];    // 256 MiB
__device__ float  g_hs[(size_t)BB * TT * HH];    //  64 MiB
__device__ float4 g_rw[(size_t)HH * HH];         //   1 MiB packed rec weights {i,f,c,o}
__device__ __nv_bfloat16 g_bhi[(size_t)NG * FF]; // 1.6 MiB: kernel^T hi [n][k]
__device__ __nv_bfloat16 g_blo[(size_t)NG * FF]; // 1.6 MiB
__device__ __nv_bfloat16 g_ahi[(size_t)BB * TT * FF]; // 98 MiB: x hi [m][k]
__device__ __nv_bfloat16 g_alo[(size_t)BB * TT * FF]; // 98 MiB

// ---------------------------------------------------------------------------
// helpers
// ---------------------------------------------------------------------------
__device__ __forceinline__ uint32_t smem_u32(const void* p) {
    uint32_t a;
    asm("{ .reg .u64 t; cvta.to.shared.u64 t, %1; cvt.u32.u64 %0, t; }" : "=r"(a) : "l"(p));
    return a;
}
__device__ __forceinline__ void f2bf_hilo(float x, uint16_t& h, uint16_t& l) {
    __nv_bfloat16 hb = __float2bfloat16(x);
    h = __bfloat16_as_ushort(hb);
    l = __bfloat16_as_ushort(__float2bfloat16(x - __bfloat162float(hb)));
}
__device__ __forceinline__ float fsig(float x) {
    return __fdividef(1.f, 1.f + __expf(-x));
}
__device__ __forceinline__ float ftanh(float x) {
    x = fminf(fmaxf(x, -15.f), 15.f);
    float e = __expf(-2.f * x);
    return __fdividef(1.f - e, 1.f + e);
}
__device__ __forceinline__ void mma_bf16(float* d, const uint32_t* a, const uint32_t* b) {
    asm volatile(
        "mma.sync.aligned.m16n8k16.row.col.f32.bf16.bf16.f32 "
        "{%0,%1,%2,%3}, {%4,%5,%6,%7}, {%8,%9}, {%0,%1,%2,%3};"
        : "+f"(d[0]), "+f"(d[1]), "+f"(d[2]), "+f"(d[3])
        : "r"(a[0]), "r"(a[1]), "r"(a[2]), "r"(a[3]), "r"(b[0]), "r"(b[1]));
}
// packed fp32x2 (B300 FFMA2)
__device__ __forceinline__ void ffma2(unsigned long long& d,
                                      unsigned long long a, unsigned long long b) {
    asm("fma.rn.f32x2 %0, %1, %2, %0;" : "+l"(d) : "l"(a), "l"(b));
}
__device__ __forceinline__ unsigned long long addx2(unsigned long long a,
                                                    unsigned long long b) {
    unsigned long long d;
    asm("add.rn.f32x2 %0, %1, %2;" : "=l"(d) : "l"(a), "l"(b));
    return d;
}
__device__ __forceinline__ float lof(unsigned long long v) {
    return __uint_as_float((uint32_t)v);
}
__device__ __forceinline__ float hif(unsigned long long v) {
    return __uint_as_float((uint32_t)(v >> 32));
}
__device__ __forceinline__ void cp16(uint32_t dst, const void* src) {
    asm volatile("cp.async.cg.shared.global [%0], [%1], 16;" :: "r"(dst), "l"(src));
}
#define CP_COMMIT() asm volatile("cp.async.commit_group;" ::: "memory")
#define CP_WAIT2()  asm volatile("cp.async.wait_group 2;"  ::: "memory")

// ---------------------------------------------------------------------------
// K0a: pack rec_kernel [H,4H] -> rw[k][u] float4 {i,f,c,o}
// ---------------------------------------------------------------------------
__global__ void pack_rec_kernel(const float* __restrict__ rec, float4* __restrict__ rw)
{
    int idx = blockIdx.x * blockDim.x + threadIdx.x;
    if (idx >= HH * HH) return;
    int k = idx >> 8;
    int u = idx & 255;
    const float* r = rec + (size_t)k * NG;
    rw[idx] = make_float4(r[u], r[HH + u], r[2 * HH + u], r[3 * HH + u]);
}

// ---------------------------------------------------------------------------
// K0b: split + transpose kernel [F,4H] -> g_bhi/g_blo [n][k] bf16
// ---------------------------------------------------------------------------
__global__ void pack_b_kernel(const float* __restrict__ Bm)
{
    int idx = blockIdx.x * blockDim.x + threadIdx.x;
    if (idx >= NG * FF) return;
    int n = idx / FF;
    int k = idx % FF;
    float v = Bm[(size_t)k * NG + n];
    uint16_t h, l;
    f2bf_hilo(v, h, l);
    g_bhi[idx] = __ushort_as_bfloat16(h);
    g_blo[idx] = __ushort_as_bfloat16(l);
}

// ---------------------------------------------------------------------------
// K0c: split x [m][k] fp32 -> g_ahi/g_alo bf16 (same layout)
// ---------------------------------------------------------------------------
__global__ void pack_a_kernel(const float* __restrict__ x)
{
    size_t idx = (size_t)blockIdx.x * blockDim.x + threadIdx.x;
    if (idx >= (size_t)BB * TT * FF) return;
    float v = x[idx];
    uint16_t h, l;
    f2bf_hilo(v, h, l);
    g_ahi[idx] = __ushort_as_bfloat16(h);
    g_alo[idx] = __ushort_as_bfloat16(l);
}

// ---------------------------------------------------------------------------
// K1: xw = x @ kernel + bias via mma.sync bf16x3 on pre-packed bf16 A/B,
// 4-stage cp.async pipeline, BK=16 (unchanged from R10).
// ---------------------------------------------------------------------------
#define SROW 48
#define K1_STAGE_BYTES (4 * 128 * SROW)              // 24576
#define K1_SMEM (4 * K1_STAGE_BYTES)                 // 98304

__global__ __launch_bounds__(256, 2)
void gemm_mma_kernel(const float* __restrict__ bias)
{
    extern __shared__ __align__(16) char smk[];
    const uint32_t sbase = smem_u32(smk);

    const int tid  = threadIdx.x;
    const int lane = tid & 31;
    const int wid  = tid >> 5;
    const int bx   = blockIdx.x;
    const int by   = blockIdx.y;

    const int m0w = (wid & 3) * 32;
    const int n0w = (wid >> 2) * 64;
    const int g   = lane >> 2;
    const int tq  = lane & 3;

    float d[2][8][4];
#pragma unroll
    for (int i = 0; i < 2; i++)
#pragma unroll
        for (int j = 0; j < 8; j++)
#pragma unroll
            for (int q = 0; q < 4; q++) d[i][j][q] = 0.f;

    const int r = tid >> 1;
    const int c = tid & 1;
    const size_t a_row_bytes = ((size_t)(by * 128 + r) * FF) * 2 + c * 16;
    const size_t b_row_bytes = ((size_t)(bx * 128 + r) * FF) * 2 + c * 16;
    const char* pAh = (const char*)g_ahi + a_row_bytes;
    const char* pAl = (const char*)g_alo + a_row_bytes;
    const char* pBh = (const char*)g_bhi + b_row_bytes;
    const char* pBl = (const char*)g_blo + b_row_bytes;
    const uint32_t s_off = (uint32_t)(r * SROW + c * 16);

#pragma unroll
    for (int s = 0; s < 3; s++) {
        const uint32_t sb = sbase + s * K1_STAGE_BYTES;
        const size_t gk = (size_t)s * 32;
        cp16(sb + s_off,              pAh + gk);
        cp16(sb + 6144  + s_off,      pAl + gk);
        cp16(sb + 12288 + s_off,      pBh + gk);
        cp16(sb + 18432 + s_off,      pBl + gk);
        CP_COMMIT();
    }

    for (int ic = 0; ic < NCHK; ic++) {
        CP_WAIT2();
        __syncthreads();

        {
            const int s = ic + 3;
            if (s < NCHK) {
                const uint32_t sb = sbase + (s & 3) * K1_STAGE_BYTES;
                const size_t gk = (size_t)s * 32;
                cp16(sb + s_off,         pAh + gk);
                cp16(sb + 6144  + s_off, pAl + gk);
                cp16(sb + 12288 + s_off, pBh + gk);
                cp16(sb + 18432 + s_off, pBl + gk);
            }
            CP_COMMIT();
        }

        const char* Ah = smk + (ic & 3) * K1_STAGE_BYTES;
        const char* Al = Ah + 6144;
        const char* Bh = Ah + 12288;
        const char* Bl = Ah + 18432;

        uint32_t ah[2][4], al[2][4];
#pragma unroll
        for (int i = 0; i < 2; i++) {
            const char* ab = Ah + (m0w + i * 16 + g) * SROW + tq * 4;
            ah[i][0] = *(const uint32_t*)(ab);
            ah[i][1] = *(const uint32_t*)(ab + 8 * SROW);
            ah[i][2] = *(const uint32_t*)(ab + 16);
            ah[i][3] = *(const uint32_t*)(ab + 8 * SROW + 16);
            const char* lb = Al + (m0w + i * 16 + g) * SROW + tq * 4;
            al[i][0] = *(const uint32_t*)(lb);
            al[i][1] = *(const uint32_t*)(lb + 8 * SROW);
            al[i][2] = *(const uint32_t*)(lb + 16);
            al[i][3] = *(const uint32_t*)(lb + 8 * SROW + 16);
        }
#pragma unroll
        for (int j = 0; j < 8; j++) {
            const char* bb = Bh + (n0w + j * 8 + g) * SROW + tq * 4;
            const char* bl = Bl + (n0w + j * 8 + g) * SROW + tq * 4;
            uint32_t bhf[2], blf[2];
            bhf[0] = *(const uint32_t*)(bb);
            bhf[1] = *(const uint32_t*)(bb + 16);
            blf[0] = *(const uint32_t*)(bl);
            blf[1] = *(const uint32_t*)(bl + 16);
#pragma unroll
            for (int i = 0; i < 2; i++) {
                mma_bf16(d[i][j], ah[i], bhf);
                mma_bf16(d[i][j], ah[i], blf);
                mma_bf16(d[i][j], al[i], bhf);
            }
        }
    }

#pragma unroll
    for (int j = 0; j < 8; j++) {
        const int col = bx * 128 + n0w + j * 8 + tq * 2;
        const float b0 = bias[col];
        const float b1 = bias[col + 1];
#pragma unroll
        for (int i = 0; i < 2; i++) {
            const int row = by * 128 + m0w + i * 16 + g;
            float2 v0 = make_float2(d[i][j][0] + b0, d[i][j][1] + b1);
            float2 v1 = make_float2(d[i][j][2] + b0, d[i][j][3] + b1);
            *(float2*)(g_xw + (size_t)row * NG + col)       = v0;
            *(float2*)(g_xw + (size_t)(row + 8) * NG + col) = v1;
        }
    }
}

// ---------------------------------------------------------------------------
// K2: peephole LSTM — 32 clusters x 4 CTAs, 512 threads/CTA (16 warps),
// k-split-8, hybrid weight residency:
//   warps 0-7  (ks 0-3): k in [0,128) from smem (128 KB, loaded once);
//                        also run the cell phase.
//   warps 8-15 (ks 4-7): k in [128,256) streamed from L2 with reg double
//                        buffer; reload chunk0 DURING the cell phase.
// Split cluster barrier: arrive after h-broadcast, wait after next step's
// xw loads. smem: 128K weights + 16K h2[2][256][4] dup-ull + 32K partials.
// ---------------------------------------------------------------------------
#define K2_CLU   4
#define K2_BATCH 4
#define K2_NT    512
#define K2_WSB   131072
#define K2_H2SZ  16384
#define K2_PART  32768
#define K2_SMEM  (K2_WSB + K2_H2SZ + K2_PART)   // 180224

__global__ __launch_bounds__(K2_NT, 1) __cluster_dims__(K2_CLU, 1, 1)
void lstm_hyb2_kernel(const float*  __restrict__ xw,
                      const float4* __restrict__ rw,
                      const float*  __restrict__ wci_p,
                      const float*  __restrict__ wcf_p,
                      const float*  __restrict__ wco_p,
                      float* __restrict__ hs)
{
    extern __shared__ __align__(16) char sm2[];
    char* wsm  = sm2;                       // [k<128][64 ul] ull2
    char* h2   = sm2 + K2_WSB;              // [2][256 k][4 b] dup-ull
    char* part = sm2 + K2_WSB + K2_H2SZ;    // [4 b][8 ks][64 ul] ull2

    const int tid = threadIdx.x;
    uint32_t rank;
    asm("mov.u32 %0, %%cluster_ctarank;" : "=r"(rank));
    const int cl = blockIdx.x >> 2;
    const int b0 = cl * K2_BATCH;

    const int ks = tid >> 6;            // k-eighth (0..7)
    const int ul = tid & 63;            // unit within CTA
    const int ug = (int)rank * 64 + ul;
    // cell identity (meaningful for tid < 256)
    const int cu = (tid >> 2) & 63;
    const int cb = tid & 3;
    const int uc = (int)rank * 64 + cu;

    // stage k<128 weights: wsm[k][uu]
    for (int idx = tid; idx < 128 * 64; idx += K2_NT) {
        int k  = idx >> 6;
        int uu = idx & 63;
        *(float4*)(wsm + (size_t)idx * 16) = rw[(k << 8) + (int)rank * 64 + uu];
    }
    // zero h buffer 0 (1024 ull)
    for (int i = tid; i < 1024; i += K2_NT)
        *(unsigned long long*)(h2 + (size_t)i * 8) = 0ull;

    float wci = 0.f, wcf = 0.f, wco = 0.f;
    uint32_t rem[K2_CLU] = {0u, 0u, 0u, 0u};
    const float* xc = xw;
    float* hc = hs;
    if (tid < 256) {
        wci = wci_p[uc];
        wcf = wcf_p[uc];
        wco = wco_p[uc];
        uint32_t l0 = smem_u32(h2) + (uint32_t)(uc * 4 + cb) * 8u;
#pragma unroll
        for (int r2 = 0; r2 < K2_CLU; r2++)
            asm("mapa.shared::cluster.u32 %0, %1, %2;"
                : "=r"(rem[r2]) : "r"(l0), "r"(r2));
        xc = xw + (size_t)(b0 + cb) * TT * NG;
        hc = hs + (size_t)(b0 + cb) * TT * HH + uc;
    }

    __syncthreads();
    asm volatile("barrier.cluster.arrive.aligned;" ::: "memory");
    asm volatile("barrier.cluster.wait.aligned;"   ::: "memory");

    const char* wp_s = wsm + ((size_t)((ks & 3) * 32) * 64 + ul) * 16;  // smem (ks<4)
    const char* wp_g = (const char*)(rw + (size_t)(ks * 32) * HH + ug); // global (ks>=4)

    float cstate = 0.f;

    // persistent chunk-0 preload for streaming warps (weights step-invariant)
    ulonglong2 wreg[2][8];
    if (ks >= 4) {
#pragma unroll
        for (int j = 0; j < 8; j++)
            wreg[0][j] = *(const ulonglong2*)(wp_g + (size_t)j * 4096);
    }

    for (int t = 0; t < TT; t++) {
        const int rb = t & 1;

        // this step's gate inputs (cell threads only; independent of h)
        float xv0 = 0.f, xv1 = 0.f, xv2 = 0.f, xv3 = 0.f;
        if (tid < 256) {
            xv0 = xc[uc];
            xv1 = xc[HH + uc];
            xv2 = xc[2 * HH + uc];
            xv3 = xc[3 * HH + uc];
        }

        // h(t) exchange from step t-1 completes here
        if (t > 0) {
            asm volatile("barrier.cluster.wait.aligned;" ::: "memory");
        }

        // ---- GEMV: 32 k, 4 batches ----
        unsigned long long aif[4], aco[4];
#pragma unroll
        for (int b2 = 0; b2 < 4; b2++) { aif[b2] = 0ull; aco[b2] = 0ull; }

        const char* hq = h2 + rb * (K2_H2SZ / 2) + (ks * 32) * 32;  // 32 B per k

        if (ks < 4) {
#pragma unroll 8
            for (int kk = 0; kk < 32; kk++) {
                ulonglong2 wv = *(const ulonglong2*)(wp_s + (size_t)kk * 1024);
                const char* hh = hq + kk * 32;
                ulonglong2 h01 = *(const ulonglong2*)(hh);
                ulonglong2 h23 = *(const ulonglong2*)(hh + 16);
                ffma2(aif[0], wv.x, h01.x); ffma2(aco[0], wv.y, h01.x);
                ffma2(aif[1], wv.x, h01.y); ffma2(aco[1], wv.y, h01.y);
                ffma2(aif[2], wv.x, h23.x); ffma2(aco[2], wv.y, h23.x);
                ffma2(aif[3], wv.x, h23.y); ffma2(aco[3], wv.y, h23.y);
            }
        } else {
#pragma unroll
            for (int ch = 0; ch < 4; ch++) {
                if (ch < 3) {
#pragma unroll
                    for (int j = 0; j < 8; j++)
                        wreg[(ch + 1) & 1][j] =
                            *(const ulonglong2*)(wp_g + (size_t)((ch + 1) * 8 + j) * 4096);
                }
#pragma unroll
                for (int j = 0; j < 8; j++) {
                    const int kk = ch * 8 + j;
                    ulonglong2 wv = wreg[ch & 1][j];
                    const char* hh = hq + kk * 32;
                    ulonglong2 h01 = *(const ulonglong2*)(hh);
                    ulonglong2 h23 = *(const ulonglong2*)(hh + 16);
                    ffma2(aif[0], wv.x, h01.x); ffma2(aco[0], wv.y, h01.x);
                    ffma2(aif[1], wv.x, h01.y); ffma2(aco[1], wv.y, h01.y);
                    ffma2(aif[2], wv.x, h23.x); ffma2(aco[2], wv.y, h23.x);
                    ffma2(aif[3], wv.x, h23.y); ffma2(aco[3], wv.y, h23.y);
                }
            }
        }

        // ---- publish partials: part[b][ks][ul] ----
#pragma unroll
        for (int b2 = 0; b2 < 4; b2++)
            *(ulonglong2*)(part + (size_t)((b2 * 8 + ks) * 64 + ul) * 16) =
                make_ulonglong2(aif[b2], aco[b2]);
        __syncthreads();

        if (tid < 256) {
            // ---- cell phase: one cell (uc, cb) ----
            unsigned long long sif = 0ull, sco = 0ull;
#pragma unroll
            for (int kq = 0; kq < 8; kq++) {
                ulonglong2 p =
                    *(const ulonglong2*)(part + (size_t)((cb * 8 + kq) * 64 + cu) * 16);
                sif = addx2(sif, p.x);
                sco = addx2(sco, p.y);
            }
            float zi = lof(sif), zf = hif(sif), zc = lof(sco), zo = hif(sco);

            float ig = fsig(zi + xv0 + cstate * wci);
            float fg = fsig(zf + xv1 + cstate * wcf);
            float cn = fg * cstate + ig * ftanh(zc + xv2);
            float og = fsig(zo + xv3 + cn * wco);
            float hn = og * ftanh(cn);
            cstate = cn;

            unsigned long long hdup;
            asm("mov.b64 %0, {%1, %1};" : "=l"(hdup) : "r"(__float_as_uint(hn)));
            const uint32_t wboff = (uint32_t)((rb ^ 1) * (K2_H2SZ / 2));
#pragma unroll
            for (int r2 = 0; r2 < K2_CLU; r2++)
                asm volatile("st.shared::cluster.b64 [%0], %1;"
                             :: "r"(rem[r2] + wboff), "l"(hdup) : "memory");

            hc[0] = hn;
            hc += HH;
            xc += NG;
        } else {
            // streaming warps: reload chunk 0 for the next step (overlaps cell)
#pragma unroll
            for (int j = 0; j < 8; j++)
                wreg[0][j] = *(const ulonglong2*)(wp_g + (size_t)j * 4096);
        }

        asm volatile("barrier.cluster.arrive.aligned;" ::: "memory");
    }
    // balance the final arrive
    asm volatile("barrier.cluster.wait.aligned;" ::: "memory");
}

// ---------------------------------------------------------------------------
// K3: BN(inference) -> tanh -> dense head.
// ---------------------------------------------------------------------------
__global__ __launch_bounds__(256)
void head_kernel(const float* __restrict__ hs,
                 const float* __restrict__ gamma,
                 const float* __restrict__ beta,
                 const float* __restrict__ mean,
                 const float* __restrict__ var,
                 const float* __restrict__ fc,
                 float* __restrict__ out)
{
    const int warp = (blockIdx.x * blockDim.x + threadIdx.x) >> 5;
    const int lane = threadIdx.x & 31;
    if (warp >= BB * TT) return;

    const float* hrow = hs + (size_t)warp * HH;
    float acc[CC];
#pragma unroll
    for (int c = 0; c < CC; c++) acc[c] = 0.f;

#pragma unroll
    for (int kk = 0; kk < HH / 32; kk++) {
        int k = kk * 32 + lane;
        float s = rsqrtf(var[k] + BN_EPS) * gamma[k];
        float v = tanhf((hrow[k] - mean[k]) * s + beta[k]);
#pragma unroll
        for (int c = 0; c < CC; c++)
            acc[c] += v * fc[k * CC + c];
    }
#pragma unroll
    for (int c = 0; c < CC; c++) {
#pragma unroll
        for (int off = 16; off > 0; off >>= 1)
            acc[c] += __shfl_xor_sync(0xffffffffu, acc[c], off);
    }
    if (lane == 0) {
        float* orow = out + (size_t)warp * CC;
#pragma unroll
        for (int c = 0; c < CC; c++) orow[c] = acc[c];
    }
}

// ---------------------------------------------------------------------------
extern "C" void kernel_launch(void* const* d_in, const int* in_sizes, int n_in,
                              void* d_out, int out_size)
{
    const float* x      = (const float*)d_in[0];
    const float* kernel = (const float*)d_in[1];
    const float* rec    = (const float*)d_in[2];
    const float* bias   = (const float*)d_in[3];
    const float* w_ci   = (const float*)d_in[4];
    const float* w_cf   = (const float*)d_in[5];
    const float* w_co   = (const float*)d_in[6];
    const float* gamma  = (const float*)d_in[7];
    const float* beta   = (const float*)d_in[8];
    const float* mmean  = (const float*)d_in[9];
    const float* mvar   = (const float*)d_in[10];
    const float* fc_w   = (const float*)d_in[11];
    float* out = (float*)d_out;

    float*  xw_p;
    float*  hs_p;
    float4* rw_p;
    cudaGetSymbolAddress((void**)&xw_p, g_xw);
    cudaGetSymbolAddress((void**)&hs_p, g_hs);
    cudaGetSymbolAddress((void**)&rw_p, g_rw);

    cudaFuncSetAttribute(gemm_mma_kernel,
                         cudaFuncAttributeMaxDynamicSharedMemorySize, K1_SMEM);
    cudaFuncSetAttribute(lstm_hyb2_kernel,
                         cudaFuncAttributeMaxDynamicSharedMemorySize, K2_SMEM);

    // K0: packing
    pack_rec_kernel<<<(HH * HH + 255) / 256, 256>>>(rec, rw_p);
    pack_b_kernel<<<((size_t)NG * FF + 255) / 256, 256>>>(kernel);
    pack_a_kernel<<<(unsigned)(((size_t)BB * TT * FF + 255) / 256), 256>>>(x);

    // K1: cp.async-pipelined HMMA input-projection GEMM
    dim3 g1(NG / 128, (BB * TT) / 128);
    gemm_mma_kernel<<<g1, 256, K1_SMEM>>>(bias);

    // K2: recurrence, 32 clusters x 4 CTAs x 512 threads
    lstm_hyb2_kernel<<<(BB / K2_BATCH) * K2_CLU, K2_NT, K2_SMEM>>>(
        xw_p, rw_p, w_ci, w_cf, w_co, hs_p);

    // K3: head
    int rows = BB * TT;
    head_kernel<<<(rows * 32 + 255) / 256, 256>>>(hs_p, gamma, beta, mmean, mvar, fc_w, out);
}

// round 12
// speedup vs baseline: 1.0861x; 1.0861x over previous
#include <cuda_runtime.h>
#include <cuda_bf16.h>
#include <math.h>
#include <stdint.h>

// Problem dims
#define BB   128
#define TT   512
#define FF   784
#define HH   256
#define NG   1024   // 4*H
#define CC   10
#define BN_EPS 1e-3f

// K1 GEMM tiling
#define BKC  16
#define NCHK (FF / BKC)   // 49

// Scratch (device globals; no runtime allocation allowed)
__device__ float  g_xw[(size_t)BB * TT * NG];    // 256 MiB
__device__ float  g_hs[(size_t)BB * TT * HH];    //  64 MiB
__device__ float4 g_rw[(size_t)HH * HH];         //   1 MiB packed rec weights {i,f,c,o}
__device__ __nv_bfloat16 g_bhi[(size_t)NG * FF]; // 1.6 MiB: kernel^T hi [n][k]
__device__ __nv_bfloat16 g_blo[(size_t)NG * FF]; // 1.6 MiB
__device__ __nv_bfloat16 g_ahi[(size_t)BB * TT * FF]; // 98 MiB: x hi [m][k]
__device__ __nv_bfloat16 g_alo[(size_t)BB * TT * FF]; // 98 MiB

// ---------------------------------------------------------------------------
// helpers
// ---------------------------------------------------------------------------
__device__ __forceinline__ uint32_t smem_u32(const void* p) {
    uint32_t a;
    asm("{ .reg .u64 t; cvta.to.shared.u64 t, %1; cvt.u32.u64 %0, t; }" : "=r"(a) : "l"(p));
    return a;
}
__device__ __forceinline__ void f2bf_hilo(float x, uint16_t& h, uint16_t& l) {
    __nv_bfloat16 hb = __float2bfloat16(x);
    h = __bfloat16_as_ushort(hb);
    l = __bfloat16_as_ushort(__float2bfloat16(x - __bfloat162float(hb)));
}
__device__ __forceinline__ float fsig(float x) {
    return __fdividef(1.f, 1.f + __expf(-x));
}
__device__ __forceinline__ float ftanh(float x) {
    x = fminf(fmaxf(x, -15.f), 15.f);
    float e = __expf(-2.f * x);
    return __fdividef(1.f - e, 1.f + e);
}
__device__ __forceinline__ void mma_bf16(float* d, const uint32_t* a, const uint32_t* b) {
    asm volatile(
        "mma.sync.aligned.m16n8k16.row.col.f32.bf16.bf16.f32 "
        "{%0,%1,%2,%3}, {%4,%5,%6,%7}, {%8,%9}, {%0,%1,%2,%3};"
        : "+f"(d[0]), "+f"(d[1]), "+f"(d[2]), "+f"(d[3])
        : "r"(a[0]), "r"(a[1]), "r"(a[2]), "r"(a[3]), "r"(b[0]), "r"(b[1]));
}
__device__ __forceinline__ void ldsm4(uint32_t* r, uint32_t a) {
    asm volatile("ldmatrix.sync.aligned.m8n8.x4.shared.b16 {%0,%1,%2,%3}, [%4];"
                 : "=r"(r[0]), "=r"(r[1]), "=r"(r[2]), "=r"(r[3]) : "r"(a));
}
// packed fp32x2 (B300 FFMA2)
__device__ __forceinline__ void ffma2(unsigned long long& d,
                                      unsigned long long a, unsigned long long b) {
    asm("fma.rn.f32x2 %0, %1, %2, %0;" : "+l"(d) : "l"(a), "l"(b));
}
__device__ __forceinline__ unsigned long long addx2(unsigned long long a,
                                                    unsigned long long b) {
    unsigned long long d;
    asm("add.rn.f32x2 %0, %1, %2;" : "=l"(d) : "l"(a), "l"(b));
    return d;
}
__device__ __forceinline__ float lof(unsigned long long v) {
    return __uint_as_float((uint32_t)v);
}
__device__ __forceinline__ float hif(unsigned long long v) {
    return __uint_as_float((uint32_t)(v >> 32));
}
__device__ __forceinline__ void cp16(uint32_t dst, const void* src) {
    asm volatile("cp.async.cg.shared.global [%0], [%1], 16;" :: "r"(dst), "l"(src));
}
#define CP_COMMIT() asm volatile("cp.async.commit_group;" ::: "memory")
#define CP_WAIT2()  asm volatile("cp.async.wait_group 2;"  ::: "memory")

// ---------------------------------------------------------------------------
// K0a: pack rec_kernel [H,4H] -> rw[k][u] float4 {i,f,c,o}
// ---------------------------------------------------------------------------
__global__ void pack_rec_kernel(const float* __restrict__ rec, float4* __restrict__ rw)
{
    int idx = blockIdx.x * blockDim.x + threadIdx.x;
    if (idx >= HH * HH) return;
    int k = idx >> 8;
    int u = idx & 255;
    const float* r = rec + (size_t)k * NG;
    rw[idx] = make_float4(r[u], r[HH + u], r[2 * HH + u], r[3 * HH + u]);
}

// ---------------------------------------------------------------------------
// K0b: split + transpose kernel [F,4H] -> g_bhi/g_blo [n][k] bf16
// ---------------------------------------------------------------------------
__global__ void pack_b_kernel(const float* __restrict__ Bm)
{
    int idx = blockIdx.x * blockDim.x + threadIdx.x;
    if (idx >= NG * FF) return;
    int n = idx / FF;
    int k = idx % FF;
    float v = Bm[(size_t)k * NG + n];
    uint16_t h, l;
    f2bf_hilo(v, h, l);
    g_bhi[idx] = __ushort_as_bfloat16(h);
    g_blo[idx] = __ushort_as_bfloat16(l);
}

// ---------------------------------------------------------------------------
// K0c: split x [m][k] fp32 -> g_ahi/g_alo bf16 (same layout)
// ---------------------------------------------------------------------------
__global__ void pack_a_kernel(const float* __restrict__ x)
{
    size_t idx = (size_t)blockIdx.x * blockDim.x + threadIdx.x;
    if (idx >= (size_t)BB * TT * FF) return;
    float v = x[idx];
    uint16_t h, l;
    f2bf_hilo(v, h, l);
    g_ahi[idx] = __ushort_as_bfloat16(h);
    g_alo[idx] = __ushort_as_bfloat16(l);
}

// ---------------------------------------------------------------------------
// K1: xw = x @ kernel + bias via mma.sync bf16x3, pre-packed bf16 A/B,
// 4-stage cp.async pipeline, ldmatrix.x4 fragment loads.
// ---------------------------------------------------------------------------
#define SROW 48
#define K1_STAGE_BYTES (4 * 128 * SROW)              // 24576
#define K1_SMEM (4 * K1_STAGE_BYTES)                 // 98304

__global__ __launch_bounds__(256, 2)
void gemm_mma_kernel(const float* __restrict__ bias)
{
    extern __shared__ __align__(16) char smk[];
    const uint32_t sbase = smem_u32(smk);

    const int tid  = threadIdx.x;
    const int lane = tid & 31;
    const int wid  = tid >> 5;
    const int bx   = blockIdx.x;
    const int by   = blockIdx.y;

    const int m0w = (wid & 3) * 32;
    const int n0w = (wid >> 2) * 64;
    const int g   = lane >> 2;
    const int tq  = lane & 3;

    float d[2][8][4];
#pragma unroll
    for (int i = 0; i < 2; i++)
#pragma unroll
        for (int j = 0; j < 8; j++)
#pragma unroll
            for (int q = 0; q < 4; q++) d[i][j][q] = 0.f;

    const int r = tid >> 1;
    const int c = tid & 1;
    const size_t a_row_bytes = ((size_t)(by * 128 + r) * FF) * 2 + c * 16;
    const size_t b_row_bytes = ((size_t)(bx * 128 + r) * FF) * 2 + c * 16;
    const char* pAh = (const char*)g_ahi + a_row_bytes;
    const char* pAl = (const char*)g_alo + a_row_bytes;
    const char* pBh = (const char*)g_bhi + b_row_bytes;
    const char* pBl = (const char*)g_blo + b_row_bytes;
    const uint32_t s_off = (uint32_t)(r * SROW + c * 16);

    // ldmatrix per-lane row offsets (stage-invariant)
    uint32_t a_off[2], b_off[4];
#pragma unroll
    for (int i = 0; i < 2; i++)
        a_off[i] = (uint32_t)((m0w + i * 16 + (lane & 15)) * SROW + (lane >> 4) * 16);
#pragma unroll
    for (int j2 = 0; j2 < 4; j2++)
        b_off[j2] = (uint32_t)((n0w + j2 * 16 + ((lane >> 4) * 8) + (lane & 7)) * SROW
                               + ((lane >> 3) & 1) * 16);

#pragma unroll
    for (int s = 0; s < 3; s++) {
        const uint32_t sb = sbase + s * K1_STAGE_BYTES;
        const size_t gk = (size_t)s * 32;
        cp16(sb + s_off,              pAh + gk);
        cp16(sb + 6144  + s_off,      pAl + gk);
        cp16(sb + 12288 + s_off,      pBh + gk);
        cp16(sb + 18432 + s_off,      pBl + gk);
        CP_COMMIT();
    }

    for (int ic = 0; ic < NCHK; ic++) {
        CP_WAIT2();
        __syncthreads();

        {
            const int s = ic + 3;
            if (s < NCHK) {
                const uint32_t sb = sbase + (s & 3) * K1_STAGE_BYTES;
                const size_t gk = (size_t)s * 32;
                cp16(sb + s_off,         pAh + gk);
                cp16(sb + 6144  + s_off, pAl + gk);
                cp16(sb + 12288 + s_off, pBh + gk);
                cp16(sb + 18432 + s_off, pBl + gk);
            }
            CP_COMMIT();
        }

        const uint32_t stg = sbase + (ic & 3) * K1_STAGE_BYTES;

        // A fragments (hi/lo) via ldmatrix.x4
        uint32_t ah[2][4], al[2][4];
#pragma unroll
        for (int i = 0; i < 2; i++) {
            ldsm4(ah[i], stg + a_off[i]);
            ldsm4(al[i], stg + 6144 + a_off[i]);
        }

        // B fragments per j-pair, MMA immediately (caps live registers)
#pragma unroll
        for (int j2 = 0; j2 < 4; j2++) {
            uint32_t bh4[4], bl4[4];
            ldsm4(bh4, stg + 12288 + b_off[j2]);
            ldsm4(bl4, stg + 18432 + b_off[j2]);
#pragma unroll
            for (int jj = 0; jj < 2; jj++) {
                const int j = j2 * 2 + jj;
                uint32_t bhf[2] = {bh4[jj * 2], bh4[jj * 2 + 1]};
                uint32_t blf[2] = {bl4[jj * 2], bl4[jj * 2 + 1]};
#pragma unroll
                for (int i = 0; i < 2; i++) {
                    mma_bf16(d[i][j], ah[i], bhf);
                    mma_bf16(d[i][j], ah[i], blf);
                    mma_bf16(d[i][j], al[i], bhf);
                }
            }
        }
    }

#pragma unroll
    for (int j = 0; j < 8; j++) {
        const int col = bx * 128 + n0w + j * 8 + tq * 2;
        const float b0 = bias[col];
        const float b1 = bias[col + 1];
#pragma unroll
        for (int i = 0; i < 2; i++) {
            const int row = by * 128 + m0w + i * 16 + g;
            float2 v0 = make_float2(d[i][j][0] + b0, d[i][j][1] + b1);
            float2 v1 = make_float2(d[i][j][2] + b0, d[i][j][3] + b1);
            *(float2*)(g_xw + (size_t)row * NG + col)       = v0;
            *(float2*)(g_xw + (size_t)(row + 8) * NG + col) = v1;
        }
    }
}

// ---------------------------------------------------------------------------
// K2: peephole LSTM — 32 clusters x 4 CTAs (128 SMs), 4 batches/cluster,
// k-split-4, three-tier weight residency:
//   ks 0,1      : k [0,128)   smem
//   ks 2        : k [128,176) smem + k [176,192) PERSISTENT REGISTERS
//   ks 3        : k [192,256) streamed from L2 (64 KB/step/CTA; chip 8 MB/step)
// Weights step-invariant -> persistent regs loaded once; ks3 keeps R9's
// reg double-buffer with chunk-0 reloaded during the cell phase.
// ---------------------------------------------------------------------------
#define K2_CLU   4
#define K2_BATCH 4
#define K2_WSB   (176 * 64 * 16)                 // 180224
#define K2_H2SZ  16384
#define K2_PART  16384
#define K2_SMEM  (K2_WSB + K2_H2SZ + K2_PART)    // 212992

__global__ __launch_bounds__(256, 1) __cluster_dims__(K2_CLU, 1, 1)
void lstm_hyb_kernel(const float*  __restrict__ xw,
                     const float4* __restrict__ rw,
                     const float*  __restrict__ wci_p,
                     const float*  __restrict__ wcf_p,
                     const float*  __restrict__ wco_p,
                     float* __restrict__ hs)
{
    extern __shared__ __align__(16) char sm2[];
    char* wsm  = sm2;                       // [k<176][64 ul] ull2
    char* h2   = sm2 + K2_WSB;              // [2][256 k][4 b] dup-ull
    char* part = sm2 + K2_WSB + K2_H2SZ;    // [4 b][4 ks][64 ul] ull2

    const int tid = threadIdx.x;
    uint32_t rank;
    asm("mov.u32 %0, %%cluster_ctarank;" : "=r"(rank));
    const int cl = blockIdx.x >> 2;
    const int b0 = cl * K2_BATCH;

    const int ks = tid >> 6;
    const int ul = tid & 63;
    const int ug = (int)rank * 64 + ul;
    const int cu = tid >> 2;
    const int cb = tid & 3;
    const int uc = (int)rank * 64 + cu;

    // stage k<176 weights
    for (int idx = tid; idx < 176 * 64; idx += 256) {
        int k  = idx >> 6;
        int uu = idx & 63;
        *(float4*)(wsm + (size_t)idx * 16) = rw[(k << 8) + (int)rank * 64 + uu];
    }
    for (int i = tid; i < 1024; i += 256)
        *(unsigned long long*)(h2 + (size_t)i * 8) = 0ull;

    const float wci = wci_p[uc];
    const float wcf = wcf_p[uc];
    const float wco = wco_p[uc];

    uint32_t rem[K2_CLU];
    {
        uint32_t l0 = smem_u32(h2) + (uint32_t)(uc * 4 + cb) * 8u;
#pragma unroll
        for (int r2 = 0; r2 < K2_CLU; r2++)
            asm("mapa.shared::cluster.u32 %0, %1, %2;"
                : "=r"(rem[r2]) : "r"(l0), "r"(r2));
    }

    __syncthreads();
    asm volatile("barrier.cluster.arrive.aligned;" ::: "memory");
    asm volatile("barrier.cluster.wait.aligned;"   ::: "memory");

    const char* wp_s = wsm + ((size_t)(ks * 64) * 64 + ul) * 16;        // ks<3 smem base
    const char* wp_g = (const char*)(rw + (size_t)(ks * 64) * HH + ug); // ks==3 global
    const float* xc = xw + (size_t)(b0 + cb) * TT * NG;
    float* hc = hs + (size_t)(b0 + cb) * TT * HH + uc;

    float cstate = 0.f;

    // ks==2: persistent registers for k in [176,192)
    ulonglong2 wper[16];
    if (ks == 2) {
#pragma unroll
        for (int j = 0; j < 16; j++)
            wper[j] = *(const ulonglong2*)((const char*)(rw + (size_t)(176 + j) * HH + ug));
    }
    // ks==3: streaming double buffer, chunk 0 persistent-reloaded
    ulonglong2 wreg[2][8];
    if (ks == 3) {
#pragma unroll
        for (int j = 0; j < 8; j++)
            wreg[0][j] = *(const ulonglong2*)(wp_g + (size_t)j * 4096);
    }

    for (int t = 0; t < TT; t++) {
        const int rb = t & 1;

        float xv0 = xc[uc];
        float xv1 = xc[HH + uc];
        float xv2 = xc[2 * HH + uc];
        float xv3 = xc[3 * HH + uc];

        unsigned long long aif[4], aco[4];
#pragma unroll
        for (int b2 = 0; b2 < 4; b2++) { aif[b2] = 0ull; aco[b2] = 0ull; }

        const char* hq = h2 + rb * (K2_H2SZ / 2) + (ks * 64) * 32;

        if (ks < 2) {
#pragma unroll 8
            for (int kk = 0; kk < 64; kk++) {
                ulonglong2 wv = *(const ulonglong2*)(wp_s + (size_t)kk * 1024);
                const char* hh = hq + kk * 32;
                ulonglong2 h01 = *(const ulonglong2*)(hh);
                ulonglong2 h23 = *(const ulonglong2*)(hh + 16);
                ffma2(aif[0], wv.x, h01.x); ffma2(aco[0], wv.y, h01.x);
                ffma2(aif[1], wv.x, h01.y); ffma2(aco[1], wv.y, h01.y);
                ffma2(aif[2], wv.x, h23.x); ffma2(aco[2], wv.y, h23.x);
                ffma2(aif[3], wv.x, h23.y); ffma2(aco[3], wv.y, h23.y);
            }
        } else if (ks == 2) {
#pragma unroll 8
            for (int kk = 0; kk < 48; kk++) {           // k 128..175 from smem
                ulonglong2 wv = *(const ulonglong2*)(wp_s + (size_t)kk * 1024);
                const char* hh = hq + kk * 32;
                ulonglong2 h01 = *(const ulonglong2*)(hh);
                ulonglong2 h23 = *(const ulonglong2*)(hh + 16);
                ffma2(aif[0], wv.x, h01.x); ffma2(aco[0], wv.y, h01.x);
                ffma2(aif[1], wv.x, h01.y); ffma2(aco[1], wv.y, h01.y);
                ffma2(aif[2], wv.x, h23.x); ffma2(aco[2], wv.y, h23.x);
                ffma2(aif[3], wv.x, h23.y); ffma2(aco[3], wv.y, h23.y);
            }
#pragma unroll
            for (int j = 0; j < 16; j++) {              // k 176..191 from regs
                ulonglong2 wv = wper[j];
                const char* hh = hq + (48 + j) * 32;
                ulonglong2 h01 = *(const ulonglong2*)(hh);
                ulonglong2 h23 = *(const ulonglong2*)(hh + 16);
                ffma2(aif[0], wv.x, h01.x); ffma2(aco[0], wv.y, h01.x);
                ffma2(aif[1], wv.x, h01.y); ffma2(aco[1], wv.y, h01.y);
                ffma2(aif[2], wv.x, h23.x); ffma2(aco[2], wv.y, h23.x);
                ffma2(aif[3], wv.x, h23.y); ffma2(aco[3], wv.y, h23.y);
            }
        } else {
#pragma unroll
            for (int ch = 0; ch < 8; ch++) {            // k 192..255 streamed
                if (ch < 7) {
#pragma unroll
                    for (int j = 0; j < 8; j++)
                        wreg[(ch + 1) & 1][j] =
                            *(const ulonglong2*)(wp_g + (size_t)((ch + 1) * 8 + j) * 4096);
                }
#pragma unroll
                for (int j = 0; j < 8; j++) {
                    const int kk = ch * 8 + j;
                    ulonglong2 wv = wreg[ch & 1][j];
                    const char* hh = hq + kk * 32;
                    ulonglong2 h01 = *(const ulonglong2*)(hh);
                    ulonglong2 h23 = *(const ulonglong2*)(hh + 16);
                    ffma2(aif[0], wv.x, h01.x); ffma2(aco[0], wv.y, h01.x);
                    ffma2(aif[1], wv.x, h01.y); ffma2(aco[1], wv.y, h01.y);
                    ffma2(aif[2], wv.x, h23.x); ffma2(aco[2], wv.y, h23.x);
                    ffma2(aif[3], wv.x, h23.y); ffma2(aco[3], wv.y, h23.y);
                }
            }
        }

        // publish partials
#pragma unroll
        for (int b2 = 0; b2 < 4; b2++)
            *(ulonglong2*)(part + (size_t)((b2 * 4 + ks) * 64 + ul) * 16) =
                make_ulonglong2(aif[b2], aco[b2]);

        // reload streaming chunk 0 — overlaps sync + cell + barrier
        if (ks == 3) {
#pragma unroll
            for (int j = 0; j < 8; j++)
                wreg[0][j] = *(const ulonglong2*)(wp_g + (size_t)j * 4096);
        }
        __syncthreads();

        // cell phase
        unsigned long long sif = 0ull, sco = 0ull;
#pragma unroll
        for (int kq = 0; kq < 4; kq++) {
            ulonglong2 p = *(const ulonglong2*)(part + (size_t)((cb * 4 + kq) * 64 + cu) * 16);
            sif = addx2(sif, p.x);
            sco = addx2(sco, p.y);
        }
        float zi = lof(sif), zf = hif(sif), zc = lof(sco), zo = hif(sco);

        float ig = fsig(zi + xv0 + cstate * wci);
        float fg = fsig(zf + xv1 + cstate * wcf);
        float cn = fg * cstate + ig * ftanh(zc + xv2);
        float og = fsig(zo + xv3 + cn * wco);
        float hn = og * ftanh(cn);
        cstate = cn;

        unsigned long long hdup;
        asm("mov.b64 %0, {%1, %1};" : "=l"(hdup) : "r"(__float_as_uint(hn)));
        const uint32_t wboff = (uint32_t)((rb ^ 1) * (K2_H2SZ / 2));
#pragma unroll
        for (int r2 = 0; r2 < K2_CLU; r2++)
            asm volatile("st.shared::cluster.b64 [%0], %1;"
                         :: "r"(rem[r2] + wboff), "l"(hdup) : "memory");

        hc[0] = hn;
        hc += HH;
        xc += NG;

        asm volatile("barrier.cluster.arrive.aligned;" ::: "memory");
        asm volatile("barrier.cluster.wait.aligned;"   ::: "memory");
    }
}

// ---------------------------------------------------------------------------
// K3: BN(inference) -> tanh -> dense head.
// ---------------------------------------------------------------------------
__global__ __launch_bounds__(256)
void head_kernel(const float* __restrict__ hs,
                 const float* __restrict__ gamma,
                 const float* __restrict__ beta,
                 const float* __restrict__ mean,
                 const float* __restrict__ var,
                 const float* __restrict__ fc,
                 float* __restrict__ out)
{
    const int warp = (blockIdx.x * blockDim.x + threadIdx.x) >> 5;
    const int lane = threadIdx.x & 31;
    if (warp >= BB * TT) return;

    const float* hrow = hs + (size_t)warp * HH;
    float acc[CC];
#pragma unroll
    for (int c = 0; c < CC; c++) acc[c] = 0.f;

#pragma unroll
    for (int kk = 0; kk < HH / 32; kk++) {
        int k = kk * 32 + lane;
        float s = rsqrtf(var[k] + BN_EPS) * gamma[k];
        float v = tanhf((hrow[k] - mean[k]) * s + beta[k]);
#pragma unroll
        for (int c = 0; c < CC; c++)
            acc[c] += v * fc[k * CC + c];
    }
#pragma unroll
    for (int c = 0; c < CC; c++) {
#pragma unroll
        for (int off = 16; off > 0; off >>= 1)
            acc[c] += __shfl_xor_sync(0xffffffffu, acc[c], off);
    }
    if (lane == 0) {
        float* orow = out + (size_t)warp * CC;
#pragma unroll
        for (int c = 0; c < CC; c++) orow[c] = acc[c];
    }
}

// ---------------------------------------------------------------------------
extern "C" void kernel_launch(void* const* d_in, const int* in_sizes, int n_in,
                              void* d_out, int out_size)
{
    const float* x      = (const float*)d_in[0];
    const float* kernel = (const float*)d_in[1];
    const float* rec    = (const float*)d_in[2];
    const float* bias   = (const float*)d_in[3];
    const float* w_ci   = (const float*)d_in[4];
    const float* w_cf   = (const float*)d_in[5];
    const float* w_co   = (const float*)d_in[6];
    const float* gamma  = (const float*)d_in[7];
    const float* beta   = (const float*)d_in[8];
    const float* mmean  = (const float*)d_in[9];
    const float* mvar   = (const float*)d_in[10];
    const float* fc_w   = (const float*)d_in[11];
    float* out = (float*)d_out;

    float*  xw_p;
    float*  hs_p;
    float4* rw_p;
    cudaGetSymbolAddress((void**)&xw_p, g_xw);
    cudaGetSymbolAddress((void**)&hs_p, g_hs);
    cudaGetSymbolAddress((void**)&rw_p, g_rw);

    cudaFuncSetAttribute(gemm_mma_kernel,
                         cudaFuncAttributeMaxDynamicSharedMemorySize, K1_SMEM);
    cudaFuncSetAttribute(lstm_hyb_kernel,
                         cudaFuncAttributeMaxDynamicSharedMemorySize, K2_SMEM);

    // K0: packing
    pack_rec_kernel<<<(HH * HH + 255) / 256, 256>>>(rec, rw_p);
    pack_b_kernel<<<((size_t)NG * FF + 255) / 256, 256>>>(kernel);
    pack_a_kernel<<<(unsigned)(((size_t)BB * TT * FF + 255) / 256), 256>>>(x);

    // K1: cp.async-pipelined HMMA GEMM with ldmatrix fragments
    dim3 g1(NG / 128, (BB * TT) / 128);
    gemm_mma_kernel<<<g1, 256, K1_SMEM>>>(bias);

    // K2: recurrence, 32 clusters x 4 CTAs, three-tier weight residency
    lstm_hyb_kernel<<<(BB / K2_BATCH) * K2_CLU, 256, K2_SMEM>>>(
        xw_p, rw_p, w_ci, w_cf, w_co, hs_p);

    // K3: head
    int rows = BB * TT;
    head_kernel<<<(rows * 32 + 255) / 256, 256>>>(hs_p, gamma, beta, mmean, mvar, fc_w, out);
}